// round 9
// baseline (speedup 1.0000x reference)
#include <cuda_runtime.h>
#include <cuda_fp16.h>
#include <cstdint>

// COO SpMM via direct fixed-capacity row buckets, D = 64.
// R9: scatter reverted to R7 scalar form (R8's MLP=4 showed scatter is
//     L2-op-throughput bound, not latency bound). New lever: convert b to
//     fp16 each launch and gather half2 in spmm — halves gather L2 traffic
//     (819MB -> 410MB) and fits b in aggregate L1. fp16 error ~5e-5 << 1e-3.

#define D_DIM    64
#define N_MAX    100000
#define E_MAX    3200000
#define CAP      128          // slots per row (avg degree 32, P(deg>128)~0)
#define OVF_CAP  8192

__device__ int     g_count[N_MAX];                  // zero-init at load
__device__ int2    g_bucket[(size_t)N_MAX * CAP];   // {col, float bits of val}
__device__ int     g_ovf_count;                     // zero-init at load
__device__ int4    g_ovf[OVF_CAP];                  // {row, col, valbits, 0}
__device__ __half2 g_bh[(size_t)N_MAX * 32];        // b in fp16, [N,64]

// ---- Phase 0: convert b to fp16 (runs concurrently-independent of scatter) ---

__global__ void convert_b(const float* __restrict__ b, int n64) {
    int i = blockIdx.x * blockDim.x + threadIdx.x;   // over float2 pairs
    int stride = gridDim.x * blockDim.x;
    const float2* src = reinterpret_cast<const float2*>(b);
    for (int k = i; k < n64; k += stride)
        g_bh[k] = __float22half2_rn(src[k]);
}

// ---- Phase 1: bucket scatter (R7 scalar form) ---------------------------------

__global__ void scatter_bucket(const int* __restrict__ idx,
                               const float* __restrict__ vals, int E) {
    int e = blockIdx.x * blockDim.x + threadIdx.x;
    if (e >= E) return;
    int row = idx[e];
    int col = idx[E + e];
    int vb  = __float_as_int(vals[e]);
    int pos = atomicAdd(&g_count[row], 1);
    if (pos < CAP) {
        g_bucket[(size_t)row * CAP + pos] = make_int2(col, vb);
    } else {
        int o = atomicAdd(&g_ovf_count, 1);
        if (o < OVF_CAP) g_ovf[o] = make_int4(row, col, vb, 0);
    }
}

// ---- Phase 2: one warp per row; half2 gathers (R5 loop shape preserved) ------

__global__ void __launch_bounds__(256) spmm_bucket(float* __restrict__ out, int n) {
    int warp = (blockIdx.x * blockDim.x + threadIdx.x) >> 5;
    int lane = threadIdx.x & 31;
    if (warp >= n) return;

    int cnt = g_count[warp];
    if (cnt > CAP) cnt = CAP;

    const int2* __restrict__ bkt = g_bucket + (size_t)warp * CAP;
    float a0 = 0.f, a1 = 0.f;

    #pragma unroll 4
    for (int i = 0; i < cnt; i++) {
        int2  p  = bkt[i];                    // broadcast load (L1-hot)
        float v  = __int_as_float(p.y);
        __half2 h = g_bh[(long long)p.x * 32 + lane];   // 4B gather
        float2 bv = __half22float2(h);
        a0 = fmaf(v, bv.x, a0);
        a1 = fmaf(v, bv.y, a1);
    }

    reinterpret_cast<float2*>(out)[(long long)warp * 32 + lane] =
        make_float2(a0, a1);
}

// ---- Phase 3 (tail): apply overflow (normally none) + restore counters -------

__global__ void tail_cleanup(const float* __restrict__ b,
                             float* __restrict__ out, int n) {
    int t = blockIdx.x * blockDim.x + threadIdx.x;
    int stride = gridDim.x * blockDim.x;

    int novf = g_ovf_count;
    if (novf > OVF_CAP) novf = OVF_CAP;
    for (int s = t; s < novf * 16; s += stride) {
        int  k = s >> 4;
        int  j = (s & 15) << 2;
        int4 ov = g_ovf[k];
        float v = __int_as_float(ov.z);
        const float4 bv =
            *reinterpret_cast<const float4*>(b + (long long)ov.y * D_DIM + j);
        float* dst = out + (long long)ov.x * D_DIM + j;
        asm volatile("red.global.add.v4.f32 [%0], {%1, %2, %3, %4};"
                     :: "l"(dst), "f"(bv.x * v), "f"(bv.y * v),
                        "f"(bv.z * v), "f"(bv.w * v)
                     : "memory");
    }

    // Restore state for the next graph replay (vectorized zero of g_count).
    int4* cz = reinterpret_cast<int4*>(g_count);
    for (int i = t; i < n / 4; i += stride)
        cz[i] = make_int4(0, 0, 0, 0);
    for (int i = (n / 4) * 4 + t; i < n; i += stride)
        g_count[i] = 0;
    if (t == 0) g_ovf_count = 0;
}

// ---- Launch ------------------------------------------------------------------

extern "C" void kernel_launch(void* const* d_in, const int* in_sizes, int n_in,
                              void* d_out, int out_size) {
    const int*   idx  = (const int*)d_in[0];          // [2, E]
    const float* vals = (const float*)d_in[1];        // [E]
    const float* b    = (const float*)d_in[n_in - 1]; // [N, 64]
    float*       out  = (float*)d_out;

    int E = in_sizes[1];
    int N = out_size / D_DIM;
    if (E > E_MAX) E = E_MAX;
    if (N > N_MAX) N = N_MAX;

    int eg = (E + 255) / 256;

    convert_b<<<256, 256>>>(b, N * 32);       // fp16 copy of b
    scatter_bucket<<<eg, 256>>>(idx, vals, E);

    long long threads = (long long)N * 32;
    spmm_bucket<<<(unsigned)((threads + 255) / 256), 256>>>(out, N);
    tail_cleanup<<<148, 256>>>(b, out, N);
}

// round 10
// speedup vs baseline: 1.0978x; 1.0978x over previous
#include <cuda_runtime.h>
#include <cstdint>

// COO SpMM via direct fixed-capacity row buckets, D = 64.
// R10: spmm is LSU-issue-bound (~5cyc/edge: 2 LDG + 2 wavefronts), proven by
//      fp16 bytes-halving having no effect. Vectorize bucket reads: int4 load
//      = 2 edges per LDG (1.5 LDG/edge). Scatter/tail = R7 exact.

#define D_DIM    64
#define N_MAX    100000
#define E_MAX    3200000
#define CAP      128          // slots per row (avg degree 32, P(deg>128)~0)
#define OVF_CAP  8192

__device__ int  g_count[N_MAX];                  // zero-init at load
__device__ int2 g_bucket[(size_t)N_MAX * CAP];   // {col, float bits of val}
__device__ int  g_ovf_count;                     // zero-init at load
__device__ int4 g_ovf[OVF_CAP];                  // {row, col, valbits, 0}

// ---- Phase 1: bucket scatter (R7 scalar form — at its L2-op floor) -----------

__global__ void scatter_bucket(const int* __restrict__ idx,
                               const float* __restrict__ vals, int E) {
    int e = blockIdx.x * blockDim.x + threadIdx.x;
    if (e >= E) return;
    int row = idx[e];
    int col = idx[E + e];
    int vb  = __float_as_int(vals[e]);
    int pos = atomicAdd(&g_count[row], 1);
    if (pos < CAP) {
        g_bucket[(size_t)row * CAP + pos] = make_int2(col, vb);
    } else {
        int o = atomicAdd(&g_ovf_count, 1);
        if (o < OVF_CAP) g_ovf[o] = make_int4(row, col, vb, 0);
    }
}

// ---- Phase 2: one warp per row; int4 bucket loads = 2 edges per LDG ----------

__global__ void __launch_bounds__(256) spmm_bucket(const float* __restrict__ b,
                                                   float* __restrict__ out, int n) {
    int warp = (blockIdx.x * blockDim.x + threadIdx.x) >> 5;
    int lane = threadIdx.x & 31;
    if (warp >= n) return;

    int cnt = g_count[warp];
    if (cnt > CAP) cnt = CAP;

    const int4* __restrict__ bkt4 =
        reinterpret_cast<const int4*>(g_bucket + (size_t)warp * CAP);
    const float2* __restrict__ B = reinterpret_cast<const float2*>(b);
    float a0 = 0.f, a1 = 0.f;

    int pairs = cnt >> 1;
    #pragma unroll 2
    for (int i = 0; i < pairs; i++) {
        int4  p  = bkt4[i];                   // 2 edges in one broadcast LDG
        float v0 = __int_as_float(p.y);
        float v1 = __int_as_float(p.w);
        float2 b0 = __ldg(&B[(long long)p.x * 32 + lane]);
        float2 b1 = __ldg(&B[(long long)p.z * 32 + lane]);
        a0 = fmaf(v0, b0.x, a0);
        a1 = fmaf(v0, b0.y, a1);
        a0 = fmaf(v1, b1.x, a0);
        a1 = fmaf(v1, b1.y, a1);
    }
    if (cnt & 1) {
        int2  p  = g_bucket[(size_t)warp * CAP + (cnt - 1)];
        float v  = __int_as_float(p.y);
        float2 bv = __ldg(&B[(long long)p.x * 32 + lane]);
        a0 = fmaf(v, bv.x, a0);
        a1 = fmaf(v, bv.y, a1);
    }

    reinterpret_cast<float2*>(out)[(long long)warp * 32 + lane] =
        make_float2(a0, a1);
}

// ---- Phase 3 (tail): apply overflow (normally none) + restore counters -------

__global__ void tail_cleanup(const float* __restrict__ b,
                             float* __restrict__ out, int n) {
    int t = blockIdx.x * blockDim.x + threadIdx.x;
    int stride = gridDim.x * blockDim.x;

    int novf = g_ovf_count;
    if (novf > OVF_CAP) novf = OVF_CAP;
    for (int s = t; s < novf * 16; s += stride) {
        int  k = s >> 4;
        int  j = (s & 15) << 2;
        int4 ov = g_ovf[k];
        float v = __int_as_float(ov.z);
        const float4 bv =
            *reinterpret_cast<const float4*>(b + (long long)ov.y * D_DIM + j);
        float* dst = out + (long long)ov.x * D_DIM + j;
        asm volatile("red.global.add.v4.f32 [%0], {%1, %2, %3, %4};"
                     :: "l"(dst), "f"(bv.x * v), "f"(bv.y * v),
                        "f"(bv.z * v), "f"(bv.w * v)
                     : "memory");
    }

    // Restore state for the next graph replay (vectorized zero of g_count).
    int4* cz = reinterpret_cast<int4*>(g_count);
    for (int i = t; i < n / 4; i += stride)
        cz[i] = make_int4(0, 0, 0, 0);
    for (int i = (n / 4) * 4 + t; i < n; i += stride)
        g_count[i] = 0;
    if (t == 0) g_ovf_count = 0;
}

// ---- Launch ------------------------------------------------------------------

extern "C" void kernel_launch(void* const* d_in, const int* in_sizes, int n_in,
                              void* d_out, int out_size) {
    const int*   idx  = (const int*)d_in[0];          // [2, E]
    const float* vals = (const float*)d_in[1];        // [E]
    const float* b    = (const float*)d_in[n_in - 1]; // [N, 64]
    float*       out  = (float*)d_out;

    int E = in_sizes[1];
    int N = out_size / D_DIM;
    if (E > E_MAX) E = E_MAX;
    if (N > N_MAX) N = N_MAX;

    int eg = (E + 255) / 256;

    scatter_bucket<<<eg, 256>>>(idx, vals, E);

    long long threads = (long long)N * 32;
    spmm_bucket<<<(unsigned)((threads + 255) / 256), 256>>>(b, out, N);
    tail_cleanup<<<148, 256>>>(b, out, N);
}